// round 12
// baseline (speedup 1.0000x reference)
#include <cuda_runtime.h>
#include <cuda_bf16.h>
#include <cstdint>

// ============================================================================
// ReuploadingQuantumLayer: 10-qubit statevector sim, 4 layers, B=16384.
// One warp per batch element. Split-component packed layout:
//   RE[16], IM[16] f32x2 regs/lane; pack k holds amplitudes (k,slot0),(k,slot1)
//   where slot = bit PBIT of the 5 low basis bits (PBIT chosen at compile time
//   to minimize slot-crossing gates).
// CNOT rings tracked as compile-time GF(2) basis transform (never applied).
// Layer 0 exploits |0..0>: direct product-state construction.
// All arithmetic via Blackwell packed fma.rn.f32x2 — no re/im swaps needed.
// ============================================================================

#define FULLM 0xFFFFFFFFu
typedef unsigned long long u64;

// ---------------- compile-time GF(2) linear algebra (10x10 bit matrices) ----
struct M10 { unsigned r[10]; };

__host__ __device__ constexpr M10 midentity() {
    M10 m{{0,0,0,0,0,0,0,0,0,0}};
    for (int i = 0; i < 10; i++) m.r[i] = 1u << i;
    return m;
}
__host__ __device__ constexpr M10 mmul(M10 a, M10 b) {
    M10 c{{0,0,0,0,0,0,0,0,0,0}};
    for (int i = 0; i < 10; i++) {
        unsigned v = 0;
        for (int j = 0; j < 10; j++)
            if ((a.r[i] >> j) & 1u) v ^= b.r[j];
        c.r[i] = v;
    }
    return c;
}
__host__ __device__ constexpr M10 mcnot(int c, int t) {
    M10 m = midentity();
    m.r[t] ^= (1u << c);
    return m;
}
__host__ __device__ constexpr M10 rmat() {
    M10 p = mcnot(0, 1);
    for (int c = 1; c < 10; c++) p = mmul(p, mcnot(c, (c + 1) % 10));
    return p;
}
__host__ __device__ constexpr M10 rinvmat() {
    M10 p = mcnot(9, 0);
    for (int c = 8; c >= 0; c--) p = mmul(p, mcnot(c, c + 1));
    return p;
}
// Invariant: stored[p] = true[T_l p],  T_l = (R^-1)^l,  Tinv_l = R^l
__host__ __device__ constexpr M10 tmat(int l) {
    M10 t = midentity();
    for (int k = 0; k < l; k++) t = mmul(rinvmat(), t);
    return t;
}
__host__ __device__ constexpr M10 tinvmat(int l) {
    M10 t = midentity();
    for (int k = 0; k < l; k++) t = mmul(t, rmat());
    return t;
}
__host__ __device__ constexpr unsigned t_row(int l, int q) { return tmat(l).r[q]; }
__host__ __device__ constexpr unsigned tinv_col(int l, int q) {
    M10 ti = tinvmat(l);
    unsigned v = 0;
    for (int i = 0; i < 10; i++) v |= ((ti.r[i] >> q) & 1u) << i;
    return v;
}
__host__ __device__ constexpr unsigned parity_(unsigned x) {
    x ^= x >> 16; x ^= x >> 8; x ^= x >> 4; x ^= x >> 2; x ^= x >> 1;
    return x & 1u;
}

// ---- pack-bit selection: the low bit appearing in the FEWEST gate masks ----
__host__ __device__ constexpr int count_pbit(int p) {
    int c = 0;
    for (int g = 10; g < 40; g++)
        if ((tinv_col(g / 10, g % 10) >> p) & 1u) c++;
    return c;
}
__host__ __device__ constexpr int best_pbit() {
    int bp = 0, bc = 1000;
    for (int p = 0; p < 5; p++) {
        int c = count_pbit(p);
        if (c < bc) { bc = c; bp = p; }
    }
    return bp;
}
constexpr int PBIT = best_pbit();

// remove bit P from a 5-bit mask -> 4-bit mask
__host__ __device__ constexpr unsigned compact5(unsigned m, int P) {
    return (m & ((1u << P) - 1u)) | (((m >> (P + 1)) & 31u) << P);
}
// 16-entry parity bitmap: bit k = parity(k & rmK)
__host__ __device__ constexpr unsigned blow16(unsigned rmK) {
    unsigned r = 0;
    for (unsigned k = 0; k < 16; k++) r |= parity_(k & rmK) << k;
    return r;
}

// ---------------- weight-derived trig table (batch independent) -------------
__device__ float4 g_wtab[40];   // per gate: (cos w1/2, sin w1/2, cos w0/2, sin w0/2)

__global__ void prep_kernel(const float* __restrict__ w) {
    int g = threadIdx.x;
    if (g < 40) {
        float w0 = w[2 * g + 0];
        float w1 = w[2 * g + 1];
        float4 t;
        t.x = cosf(0.5f * w1);
        t.y = sinf(0.5f * w1);
        t.z = cosf(0.5f * w0);
        t.w = sinf(0.5f * w0);
        g_wtab[g] = t;
    }
}

// ---------------- packed f32x2 primitives ------------------------------------
__device__ __forceinline__ u64 pack2(float lo, float hi) {
    u64 r;
    asm("mov.b64 %0, {%1, %2};" : "=l"(r) : "f"(lo), "f"(hi));
    return r;
}
__device__ __forceinline__ void unpack2(u64 v, float& lo, float& hi) {
    asm("mov.b64 {%0, %1}, %2;" : "=f"(lo), "=f"(hi) : "l"(v));
}
__device__ __forceinline__ u64 swp(u64 v) {   // (lo,hi) -> (hi,lo)
    float lo, hi;
    unpack2(v, lo, hi);
    return pack2(hi, lo);
}
__device__ __forceinline__ u64 fma2(u64 a, u64 b, u64 c) {
    u64 d;
    asm("fma.rn.f32x2 %0, %1, %2, %3;" : "=l"(d) : "l"(a), "l"(b), "l"(c));
    return d;
}
__device__ __forceinline__ u64 mul2(u64 a, u64 b) {
    u64 d;
    asm("mul.rn.f32x2 %0, %1, %2;" : "=l"(d) : "l"(a), "l"(b));
    return d;
}
__device__ __forceinline__ u64 add2(u64 a, u64 b) {
    u64 d;
    asm("add.rn.f32x2 %0, %1, %2;" : "=l"(d) : "l"(a), "l"(b));
    return d;
}
__device__ __forceinline__ u64 shx64(u64 v, int m) {
    return __shfl_xor_sync(FULLM, v, m);
}

// element update, side bit t (compile-time after unroll):
//   RE' = alx*REa - tau*aly*IMa - tau*bex*REb - bey*IMb
//   IM' = alx*IMa + tau*aly*REa - tau*bex*IMb + bey*REb
// TAY0/TAY1 = +/- tau-packed aly; TBX0/TBX1 = +/- tau-packed bex.
#define UPD(t, REa, IMa, REb, IMb, REo, IMo) do {                               \
    u64 _tay  = (t) ? TAY1 : TAY0;                                              \
    u64 _ntay = (t) ? TAY0 : TAY1;                                              \
    u64 _ntbx = (t) ? TBX0 : TBX1;                                              \
    u64 _ro = fma2(ALX, (REa), fma2(_ntay, (IMa), fma2(_ntbx, (REb), mul2(NBEY, (IMb))))); \
    u64 _io = fma2(ALX, (IMa), fma2(_tay,  (REa), fma2(_ntbx, (IMb), mul2(BEY,  (REb))))); \
    (REo) = _ro; (IMo) = _io; } while (0)

// ---------------- one gate (fully unrolled, masks are immediates) ------------
template <int G>
__device__ __forceinline__ void apply_gate(u64 (&RE)[16], u64 (&IM)[16], int lane,
                                           float2 A0, float2 B0,
                                           float2 A1, float2 B1) {
    constexpr unsigned rm    = t_row(G / 10, G % 10);
    constexpr unsigned v     = tinv_col(G / 10, G % 10);
    constexpr unsigned vlow  = v & 31u,  vhigh = v >> 5;
    constexpr unsigned rml   = rm & 31u, rmh   = rm >> 5;
    constexpr unsigned vP    = (vlow >> PBIT) & 1u;
    constexpr unsigned vK    = compact5(vlow, PBIT);
    constexpr unsigned rmP   = (rml >> PBIT) & 1u;
    constexpr unsigned rmK   = compact5(rml, PBIT);
    constexpr unsigned PARK  = blow16(rmK);
    constexpr int src = G & 31;

    // broadcast alpha, beta (computed by owner lane)
    float alx = __shfl_sync(FULLM, (G < 32) ? A0.x : A1.x, src);
    float aly = __shfl_sync(FULLM, (G < 32) ? A0.y : A1.y, src);
    float bex = __shfl_sync(FULLM, (G < 32) ? B0.x : B1.x, src);
    float bey = __shfl_sync(FULLM, (G < 32) ? B0.y : B1.y, src);

    bool blane = (__popc(lane & (int)rmh) & 1) != 0;
    float e  = blane ? -1.f : 1.f;
    float ey = e * aly, ex = e * bex;
    float sy = rmP ? -ey : ey;      // hi-slot sign factor
    float sx = rmP ? -ex : ex;

    u64 ALX  = pack2(alx, alx);
    u64 BEY  = pack2(bey, bey);
    u64 NBEY = pack2(-bey, -bey);
    u64 TAY0 = pack2(ey, sy),  TAY1 = pack2(-ey, -sy);
    u64 TBX0 = pack2(ex, sx),  TBX1 = pack2(-ex, -sx);

    if (vhigh == 0u) {
        if (vK == 0u) {
            // vP==1: partner is the other slot of the same pack
            #pragma unroll
            for (int k = 0; k < 16; k++) {
                u64 ra = RE[k], ia = IM[k];
                u64 rb = swp(ra), ib = swp(ia);
                UPD((PARK >> k) & 1u, ra, ia, rb, ib, RE[k], IM[k]);
            }
        } else {
            constexpr unsigned hb = vK & (0u - vK);
            #pragma unroll
            for (int k = 0; k < 16; k++) {
                if ((k & (int)hb) == 0) {
                    const int kb = k ^ (int)vK;
                    u64 ra = RE[k],  ia = IM[k];
                    u64 rb = RE[kb], ib = IM[kb];
                    u64 rbS = vP ? swp(rb) : rb, ibS = vP ? swp(ib) : ib;
                    u64 raS = vP ? swp(ra) : ra, iaS = vP ? swp(ia) : ia;
                    UPD((PARK >> k)  & 1u, ra, ia, rbS, ibS, RE[k],  IM[k]);
                    UPD((PARK >> kb) & 1u, rb, ib, raS, iaS, RE[kb], IM[kb]);
                }
            }
        }
    } else {
        if (vK == 0u) {
            #pragma unroll
            for (int k = 0; k < 16; k++) {
                u64 pr = shx64(RE[k], (int)vhigh);
                u64 pi = shx64(IM[k], (int)vhigh);
                if (vP) { pr = swp(pr); pi = swp(pi); }
                u64 ra = RE[k], ia = IM[k];
                UPD((PARK >> k) & 1u, ra, ia, pr, pi, RE[k], IM[k]);
            }
        } else {
            // pair-lockstep: all shuffles of a pair read pre-update values
            constexpr unsigned hb = vK & (0u - vK);
            #pragma unroll
            for (int k = 0; k < 16; k++) {
                if ((k & (int)hb) == 0) {
                    const int kb = k ^ (int)vK;
                    u64 pAr = shx64(RE[kb], (int)vhigh);
                    u64 pAi = shx64(IM[kb], (int)vhigh);
                    u64 pBr = shx64(RE[k],  (int)vhigh);
                    u64 pBi = shx64(IM[k],  (int)vhigh);
                    if (vP) { pAr = swp(pAr); pAi = swp(pAi);
                              pBr = swp(pBr); pBi = swp(pBi); }
                    u64 ra = RE[k], ia = IM[k], rb = RE[kb], ib = IM[kb];
                    UPD((PARK >> k)  & 1u, ra, ia, pAr, pAi, RE[k],  IM[k]);
                    UPD((PARK >> kb) & 1u, rb, ib, pBr, pBi, RE[kb], IM[kb]);
                }
            }
        }
    }
}

template <int G>
struct GLoop {
    static __device__ __forceinline__ void run(u64 (&RE)[16], u64 (&IM)[16], int lane,
                                               float2 A0, float2 B0,
                                               float2 A1, float2 B1) {
        apply_gate<G>(RE, IM, lane, A0, B0, A1, B1);
        GLoop<G + 1>::run(RE, IM, lane, A0, B0, A1, B1);
    }
};
template <>
struct GLoop<40> {
    static __device__ __forceinline__ void run(u64 (&)[16], u64 (&)[16], int,
                                               float2, float2, float2, float2) {}
};

// ---------------- measurement: <Z_q> with final transform T_4 ----------------
template <int Q>
__device__ __forceinline__ float zsum(const u64 (&pr2)[16], int lane) {
    constexpr unsigned fm   = t_row(4, Q);
    constexpr unsigned rml  = fm & 31u, rmh = fm >> 5;
    constexpr unsigned rmP  = (rml >> PBIT) & 1u;
    constexpr unsigned rmK  = compact5(rml, PBIT);
    constexpr unsigned PARK = blow16(rmK);
    const u64 SGNp = pack2(1.f,  rmP ? -1.f :  1.f);
    const u64 SGNm = pack2(-1.f, rmP ?  1.f : -1.f);
    u64 acc0 = 0ull, acc1 = 0ull;
    #pragma unroll
    for (int k = 0; k < 8; k++)
        acc0 = fma2(pr2[k], ((PARK >> k) & 1u) ? SGNm : SGNp, acc0);
    #pragma unroll
    for (int k = 8; k < 16; k++)
        acc1 = fma2(pr2[k], ((PARK >> k) & 1u) ? SGNm : SGNp, acc1);
    float lo, hi;
    unpack2(add2(acc0, acc1), lo, hi);
    float s = lo + hi;
    if (__popc(lane & (int)rmh) & 1) s = -s;
    return s;
}

template <int Q>   // processes Q and Q+1 together (Q even)
struct M2 {
    static __device__ __forceinline__ void run(const u64 (&pr2)[16], int lane,
                                               float* __restrict__ outp) {
        float sA = zsum<Q>(pr2, lane);
        float sB = zsum<Q + 1>(pr2, lane);
        u64 v = pack2(sA, sB);
        #pragma unroll
        for (int off = 16; off; off >>= 1)
            v = add2(v, shx64(v, off));
        if (lane == 0)
            *reinterpret_cast<u64*>(outp + Q) = v;   // (b*10+Q)*4 is 8B-aligned
        M2<Q + 2>::run(pr2, lane, outp);
    }
};
template <>
struct M2<10> {
    static __device__ __forceinline__ void run(const u64 (&)[16], int, float*) {}
};

// compute (alpha, beta) for one gate from its angle trig + weight trig
__device__ __forceinline__ void gate_coeffs(float ca, float sa, float4 wt,
                                            float2& al, float2& be) {
    float cw = wt.x, sw = wt.y, cph = wt.z, sph = wt.w;
    float A = cw * ca, B = sw * sa, C = sw * ca, D = cw * sa;
    al = make_float2((A - B) * cph, -(A + B) * sph);
    be = make_float2((C + D) * cph,  (D - C) * sph);
}

// ---------------- main kernel ------------------------------------------------
__global__ void __launch_bounds__(128, 4)
qsim_kernel(const float* __restrict__ x, float* __restrict__ out, int B) {
    const int lane = threadIdx.x & 31;
    const int b = blockIdx.x * (blockDim.x >> 5) + (threadIdx.x >> 5);
    if (b >= B) return;

    const float* xb = x + (size_t)b * 40;
    const float PI_F = 3.14159265358979f;

    // ---- per-gate coefficients: lane g owns gate g (set0) and gate 32+g (set1)
    float ca0, sa0;
    __sincosf(0.5f * PI_F * atanf(xb[lane]), &sa0, &ca0);
    float2 A0, B0;
    gate_coeffs(ca0, sa0, g_wtab[lane], A0, B0);

    float2 A1 = make_float2(1.f, 0.f), B1 = make_float2(0.f, 0.f);
    if (lane < 8) {
        float ca1, sa1;
        __sincosf(0.5f * PI_F * atanf(xb[32 + lane]), &sa1, &ca1);
        gate_coeffs(ca1, sa1, g_wtab[32 + lane], A1, B1);
    }

    // ---- layer 0: product state, built directly in split layout ----
    // lane factor over qubits 5..9 (selected by lane bits), scalar complex
    float fzr, fzi;
    {
        float ux = __shfl_sync(FULLM, A0.x, 5), uy = __shfl_sync(FULLM, A0.y, 5);
        float wx = __shfl_sync(FULLM, B0.x, 5), wy = __shfl_sync(FULLM, B0.y, 5);
        fzr = (lane & 1) ? wx : ux;
        fzi = (lane & 1) ? wy : uy;
        #pragma unroll
        for (int j = 1; j < 5; j++) {
            const int srcl = 5 + j;
            float ax = __shfl_sync(FULLM, A0.x, srcl), ay = __shfl_sync(FULLM, A0.y, srcl);
            float bx = __shfl_sync(FULLM, B0.x, srcl), by = __shfl_sync(FULLM, B0.y, srcl);
            float cx = ((lane >> j) & 1) ? bx : ax;
            float cy = ((lane >> j) & 1) ? by : ay;
            float nr = fzr * cx - fzi * cy;
            float ni = fzr * cy + fzi * cx;
            fzr = nr; fzi = ni;
        }
    }

    u64 RE[16], IM[16];
    // slot qubit = PBIT
    {
        float ax = __shfl_sync(FULLM, A0.x, PBIT), ay = __shfl_sync(FULLM, A0.y, PBIT);
        float bx = __shfl_sync(FULLM, B0.x, PBIT), by = __shfl_sync(FULLM, B0.y, PBIT);
        RE[0] = pack2(fzr * ax - fzi * ay, fzr * bx - fzi * by);
        IM[0] = pack2(fzr * ay + fzi * ax, fzr * by + fzi * bx);
    }
    // pack-bit doubling over remaining low qubits
    #pragma unroll
    for (int j = 0; j < 4; j++) {
        const int q = (j < PBIT) ? j : j + 1;
        float u0x = __shfl_sync(FULLM, A0.x, q), u0y = __shfl_sync(FULLM, A0.y, q);
        float u1x = __shfl_sync(FULLM, B0.x, q), u1y = __shfl_sync(FULLM, B0.y, q);
        u64 U0X = pack2(u0x, u0x), U0Y = pack2(u0y, u0y), NU0Y = pack2(-u0y, -u0y);
        u64 U1X = pack2(u1x, u1x), U1Y = pack2(u1y, u1y), NU1Y = pack2(-u1y, -u1y);
        #pragma unroll
        for (int k = 0; k < 16; k++) {
            if (k < (1 << j)) {
                u64 rr = RE[k], ii = IM[k];
                RE[k | (1 << j)] = fma2(U1X, rr, mul2(NU1Y, ii));
                IM[k | (1 << j)] = fma2(U1X, ii, mul2(U1Y,  rr));
                RE[k]            = fma2(U0X, rr, mul2(NU0Y, ii));
                IM[k]            = fma2(U0X, ii, mul2(U0Y,  rr));
            }
        }
    }

    // ---- layers 1..3 (gates 10..39) ----
    GLoop<10>::run(RE, IM, lane, A0, B0, A1, B1);

    // ---- probabilities (packed) + <Z_q> ----
    u64 pr2[16];
    #pragma unroll
    for (int k = 0; k < 16; k++)
        pr2[k] = fma2(RE[k], RE[k], mul2(IM[k], IM[k]));

    M2<0>::run(pr2, lane, out + (size_t)b * 10);
}

// ---------------- launch -----------------------------------------------------
extern "C" void kernel_launch(void* const* d_in, const int* in_sizes, int n_in,
                              void* d_out, int out_size) {
    const float* x = (const float*)d_in[0];   // [B, 40] fp32
    const float* w = (const float*)d_in[1];   // [4, 10, 2] fp32
    float* out = (float*)d_out;               // [B, 10] fp32

    int B = in_sizes[0] / 40;
    prep_kernel<<<1, 64>>>(w);
    const int THREADS = 128;
    int wpb = THREADS / 32;
    int blocks = (B + wpb - 1) / wpb;
    qsim_kernel<<<blocks, THREADS>>>(x, out, B);
}